// round 7
// baseline (speedup 1.0000x reference)
#include <cuda_runtime.h>
#include <cstdint>

// ---------------------------------------------------------------------------
// LokrLinear: out = x @ (base_kernel + 2.0 * kron(lora_A@lora_B, O)) + bias
//
// Base-ISA path (tcgen05 is 'a'-gated; harness builds compute_103 PTX):
//   1) WL = lora_A @ lora_B (16x16)
//   2) Wt[n][k] = round_tf32(base[k][n] + 2*WL[k/256][n/256]*O[k%256][n%256])
//   3) Xc = round_tf32(x)            (RNA rounding avoids HMMA truncation bias)
//   4) out = Xc @ Wt^T + bias via mma.sync.m16n8k8.tf32, cp.async 3-stage
//      pipeline, SW128-swizzled smem, ldmatrix fragment loads.
//
// R7: back to R5 shape (128x128 block, 64x32 warp tile, occ 2 — best so far),
// plus explicit fragment double-buffering across kk and ldsm-before-fill
// ordering, so the ldsm->mma dependency stall is hidden under MMA issue.
// ---------------------------------------------------------------------------

static constexpr int MDIM = 16384;
static constexpr int KDIM = 4096;
static constexpr int NDIM = 4096;

static constexpr int BM = 128;
static constexpr int BN = 128;
static constexpr int BK = 32;                 // 32 tf32 = 128B row (SW128 atom)
static constexpr int STAGES = 3;
static constexpr int NKITER = KDIM / BK;      // 128
static constexpr int A_STAGE_BYTES = BM * BK * 4;   // 16384
static constexpr int B_STAGE_BYTES = BN * BK * 4;   // 16384
static constexpr int STAGE_BYTES = A_STAGE_BYTES + B_STAGE_BYTES; // 32768
static constexpr int SMEM_TOTAL = STAGES * STAGE_BYTES;           // 98304

// Device scratch (static __device__ arrays are the allowed scratch mechanism)
__device__ float g_WL[256];                           // (A@B) 16x16
__device__ float g_Wt[(size_t)NDIM * (size_t)KDIM];   // W_eff^T: [N][K], K contiguous
__device__ float g_Xc[(size_t)MDIM * (size_t)KDIM];   // tf32-rounded x

// ---------------------------------------------------------------------------
// Helpers
// ---------------------------------------------------------------------------
__device__ __forceinline__ uint32_t smem_u32(const void* p) {
    uint32_t a;
    asm("{ .reg .u64 t; cvta.to.shared.u64 t, %1; cvt.u32.u64 %0, t; }" : "=r"(a) : "l"(p));
    return a;
}

__device__ __forceinline__ float cvt_tf32(float x) {
    uint32_t o;
    asm("cvt.rna.tf32.f32 %0, %1;" : "=r"(o) : "f"(x));
    return __uint_as_float(o);
}

__device__ __forceinline__ void cp16(uint32_t saddr, const float* g) {
    asm volatile("cp.async.cg.shared.global [%0], [%1], 16;\n" :: "r"(saddr), "l"(g));
}
#define CP_COMMIT() asm volatile("cp.async.commit_group;\n" ::: "memory")

__device__ __forceinline__ void ldsm_x4(uint32_t& r0, uint32_t& r1, uint32_t& r2, uint32_t& r3,
                                        uint32_t addr) {
    asm volatile("ldmatrix.sync.aligned.m8n8.x4.shared.b16 {%0,%1,%2,%3}, [%4];\n"
                 : "=r"(r0), "=r"(r1), "=r"(r2), "=r"(r3) : "r"(addr));
}

__device__ __forceinline__ void mma_tf32(float& d0, float& d1, float& d2, float& d3,
                                         uint32_t a0, uint32_t a1, uint32_t a2, uint32_t a3,
                                         uint32_t b0, uint32_t b1) {
    asm volatile(
        "mma.sync.aligned.m16n8k8.row.col.f32.tf32.tf32.f32 "
        "{%0,%1,%2,%3}, {%4,%5,%6,%7}, {%8,%9}, {%0,%1,%2,%3};\n"
        : "+f"(d0), "+f"(d1), "+f"(d2), "+f"(d3)
        : "r"(a0), "r"(a1), "r"(a2), "r"(a3), "r"(b0), "r"(b1));
}

__device__ __forceinline__ uint32_t sw128(uint32_t off) {
    return off ^ ((off >> 3) & 0x70);
}

// ---------------------------------------------------------------------------
// Kernel 1: WL = lora_A @ lora_B (16x16)
// ---------------------------------------------------------------------------
__global__ void lokr_compute_wl(const float* __restrict__ A, const float* __restrict__ B) {
    const int i = threadIdx.x >> 4, j = threadIdx.x & 15;
    float s = 0.f;
#pragma unroll
    for (int r = 0; r < 16; r++) s += A[i * 16 + r] * B[r * 16 + j];
    g_WL[threadIdx.x] = s;
}

// ---------------------------------------------------------------------------
// Kernel 2: Wt[n][k] = round_tf32(base[k][n] + 2*WL[k/256][n/256]*O[k%256][n%256])
// (transpose through padded SMEM tiles; all global accesses coalesced)
// ---------------------------------------------------------------------------
__global__ void lokr_build_wt(const float* __restrict__ base, const float* __restrict__ O) {
    __shared__ float tb[32][33];
    __shared__ float to[32][33];
    const int k0 = blockIdx.x * 32;
    const int n0 = blockIdx.y * 32;
    const int tx = threadIdx.x, ty = threadIdx.y;
    const float wl2 = 2.0f * g_WL[(k0 >> 8) * 16 + (n0 >> 8)];
    const int p0 = k0 & 255, q0 = n0 & 255;
#pragma unroll
    for (int i = 0; i < 4; i++) {
        const int r = ty + i * 8;
        tb[r][tx] = base[(size_t)(k0 + r) * NDIM + n0 + tx];
        to[r][tx] = O[(p0 + r) * 256 + q0 + tx];
    }
    __syncthreads();
#pragma unroll
    for (int i = 0; i < 4; i++) {
        const int r = ty + i * 8;   // n-offset within tile
        g_Wt[(size_t)(n0 + r) * KDIM + k0 + tx] = cvt_tf32(tb[tx][r] + wl2 * to[tx][r]);
    }
}

// ---------------------------------------------------------------------------
// Kernel 3: Xc = round_tf32(x), vectorized
// ---------------------------------------------------------------------------
__global__ void lokr_cvt_x(const float4* __restrict__ x) {
    const size_t i = (size_t)blockIdx.x * blockDim.x + threadIdx.x;
    float4 v = x[i];
    v.x = cvt_tf32(v.x); v.y = cvt_tf32(v.y);
    v.z = cvt_tf32(v.z); v.w = cvt_tf32(v.w);
    reinterpret_cast<float4*>(g_Xc)[i] = v;
}

// ---------------------------------------------------------------------------
// Kernel 4: TF32 mma.sync GEMM. BM=128 x BN=128 x BK=32, 3-stage cp.async,
// 2 CTAs/SM. 256 threads = 8 warps; warp grid 2(m) x 4(n); warp tile 64x32.
// Fragment double-buffering across the 4 kk-steps of each k-iteration.
// ---------------------------------------------------------------------------
__device__ __forceinline__ void gemm_fill_stage(uint32_t smem_base, int stage, int kt,
                                                const float* Abase, const float* Bbase,
                                                int tid) {
    const uint32_t sa = smem_base + stage * STAGE_BYTES;
    const uint32_t sb = sa + A_STAGE_BYTES;
    const int k0 = kt * BK;
    // A: 128 rows x 8 16B-chunks = 1024 chunks; 4 per thread
#pragma unroll
    for (int j = 0; j < 4; j++) {
        const int c = j * 256 + tid;
        const int row = c >> 3, col4 = c & 7;
        cp16(sa + sw128((uint32_t)(row * 128 + col4 * 16)),
             Abase + (size_t)row * KDIM + k0 + col4 * 4);
    }
    // B: same shape
#pragma unroll
    for (int j = 0; j < 4; j++) {
        const int c = j * 256 + tid;
        const int row = c >> 3, col4 = c & 7;
        cp16(sb + sw128((uint32_t)(row * 128 + col4 * 16)),
             Bbase + (size_t)row * KDIM + k0 + col4 * 4);
    }
    CP_COMMIT();
}

__global__ void __launch_bounds__(256, 2)
lokr_gemm_tf32(const float* __restrict__ bias, float* __restrict__ out) {
    extern __shared__ char smem[];
    const uint32_t smem_base = smem_u32(smem);
    const int tid = threadIdx.x;
    const int lane = tid & 31, wid = tid >> 5;
    const int warp_m = (wid & 1) * 64;   // 2 warps along m
    const int warp_n = (wid >> 1) * 32;  // 4 warps along n
    const int n0 = blockIdx.x * BN;
    const int m0 = blockIdx.y * BM;

    const float* Abase = g_Xc + (size_t)m0 * KDIM;
    const float* Bbase = g_Wt + (size_t)n0 * KDIM;

    // Per-thread ldmatrix byte offsets (before swizzle, before kk term).
    uint32_t aOff[4], bOff[2];
    {
        const uint32_t colp = ((lane >> 4) & 1) * 16;  // k-half select (16B)
#pragma unroll
        for (int i = 0; i < 4; i++)
            aOff[i] = (uint32_t)((warp_m + i * 16 + (lane & 15)) * 128) + colp;
#pragma unroll
        for (int j = 0; j < 2; j++)
            bOff[j] = (uint32_t)((warp_n + j * 16 + (lane & 15)) * 128) + colp;
    }

    float d[4][4][4];
#pragma unroll
    for (int i = 0; i < 4; i++)
#pragma unroll
        for (int n = 0; n < 4; n++)
#pragma unroll
            for (int c = 0; c < 4; c++) d[i][n][c] = 0.f;

    // Double-buffered fragments
    uint32_t a[2][4][4];
    uint32_t b[2][4][2];

    // Prologue: fill STAGES-1 stages
#pragma unroll
    for (int s = 0; s < STAGES - 1; s++) gemm_fill_stage(smem_base, s, s, Abase, Bbase, tid);

    for (int kt = 0; kt < NKITER; kt++) {
        const int s = kt % STAGES;
        asm volatile("cp.async.wait_group %0;\n" :: "n"(STAGES - 2) : "memory");
        __syncthreads();

        const uint32_t sa = smem_base + s * STAGE_BYTES;
        const uint32_t sb = sa + A_STAGE_BYTES;

        // Load kk=0 fragments FIRST (dependent chain starts immediately)...
#pragma unroll
        for (int i = 0; i < 4; i++)
            ldsm_x4(a[0][i][0], a[0][i][1], a[0][i][2], a[0][i][3], sa + sw128(aOff[i]));
#pragma unroll
        for (int j = 0; j < 2; j++) {
            uint32_t r0, r1, r2, r3;
            ldsm_x4(r0, r1, r2, r3, sb + sw128(bOff[j]));
            b[0][2 * j][0] = r0; b[0][2 * j + 1][0] = r1;
            b[0][2 * j][1] = r2; b[0][2 * j + 1][1] = r3;
        }

        // ...then issue the next stage's cp.async (overlaps ldsm latency + MMAs)
        if (kt + STAGES - 1 < NKITER)
            gemm_fill_stage(smem_base, (kt + STAGES - 1) % STAGES, kt + STAGES - 1,
                            Abase, Bbase, tid);
        else
            CP_COMMIT();  // empty group keeps wait_group accounting uniform

#pragma unroll
        for (int kk = 0; kk < BK / 8; kk++) {
            const int cur = kk & 1, nxt = cur ^ 1;
            // Prefetch kk+1 fragments into the alternate buffer
            if (kk < BK / 8 - 1) {
                const uint32_t kb = (uint32_t)((kk + 1) * 32);
#pragma unroll
                for (int i = 0; i < 4; i++)
                    ldsm_x4(a[nxt][i][0], a[nxt][i][1], a[nxt][i][2], a[nxt][i][3],
                            sa + sw128(aOff[i] + kb));
#pragma unroll
                for (int j = 0; j < 2; j++) {
                    uint32_t r0, r1, r2, r3;
                    ldsm_x4(r0, r1, r2, r3, sb + sw128(bOff[j] + kb));
                    b[nxt][2 * j][0] = r0; b[nxt][2 * j + 1][0] = r1;
                    b[nxt][2 * j][1] = r2; b[nxt][2 * j + 1][1] = r3;
                }
            }
            // MMAs on current buffer (ldsm above retires underneath)
#pragma unroll
            for (int i = 0; i < 4; i++)
#pragma unroll
                for (int n = 0; n < 4; n++)
                    mma_tf32(d[i][n][0], d[i][n][1], d[i][n][2], d[i][n][3],
                             a[cur][i][0], a[cur][i][1], a[cur][i][2], a[cur][i][3],
                             b[cur][n][0], b[cur][n][1]);
        }
    }

    // Epilogue: add bias, store float2 per (row, n-block)
#pragma unroll
    for (int i = 0; i < 4; i++) {
        const int row = m0 + warp_m + i * 16 + (lane >> 2);
#pragma unroll
        for (int n = 0; n < 4; n++) {
            const int col = n0 + warp_n + n * 8 + (lane & 3) * 2;
            const float bv0 = bias[col], bv1 = bias[col + 1];
            float2 v0 = make_float2(d[i][n][0] + bv0, d[i][n][1] + bv1);
            float2 v1 = make_float2(d[i][n][2] + bv0, d[i][n][3] + bv1);
            *reinterpret_cast<float2*>(out + (size_t)row * NDIM + col) = v0;
            *reinterpret_cast<float2*>(out + (size_t)(row + 8) * NDIM + col) = v1;
        }
    }
}

// ---------------------------------------------------------------------------
// Launch
// ---------------------------------------------------------------------------
extern "C" void kernel_launch(void* const* d_in, const int* in_sizes, int n_in,
                              void* d_out, int out_size) {
    (void)in_sizes; (void)n_in; (void)out_size;
    const float* x    = (const float*)d_in[0];
    const float* base = (const float*)d_in[1];
    const float* bias = (const float*)d_in[2];
    const float* la   = (const float*)d_in[3];
    const float* lb   = (const float*)d_in[4];
    const float* O    = (const float*)d_in[5];
    float* out = (float*)d_out;

    lokr_compute_wl<<<1, 256>>>(la, lb);

    dim3 gw(KDIM / 32, NDIM / 32);
    lokr_build_wt<<<gw, dim3(32, 8)>>>(base, O);

    const size_t n4 = (size_t)MDIM * KDIM / 4;   // 16M float4
    lokr_cvt_x<<<(unsigned)(n4 / 256), 256>>>((const float4*)x);

    cudaFuncSetAttribute(lokr_gemm_tf32, cudaFuncAttributeMaxDynamicSharedMemorySize, SMEM_TOTAL);
    dim3 gg(NDIM / BN, MDIM / BM);
    lokr_gemm_tf32<<<gg, 256, SMEM_TOTAL>>>(bias, out);
}

// round 9
// speedup vs baseline: 1.0666x; 1.0666x over previous
#include <cuda_runtime.h>
#include <cstdint>

// ---------------------------------------------------------------------------
// LokrLinear: out = x @ (base_kernel + 2.0 * kron(lora_A@lora_B, O)) + bias
//
// Base-ISA path (tcgen05 is 'a'-gated; harness builds compute_103 PTX):
//   1) WL = lora_A @ lora_B (16x16)
//   2) Wt[n][k] = round_tf32(base[k][n] + 2*WL[k/256][n/256]*O[k%256][n%256])
//   3) Xc = round_tf32(x)            (RNA rounding avoids HMMA truncation bias)
//   4) out = Xc @ Wt^T + bias via mma.sync.m16n8k8.tf32, cp.async 3-stage
//      pipeline, SW128-swizzled smem, ldmatrix fragment loads.
//
// R8: R5 config (128x128 block, 64x32 warp tile, occ 2 — best so far) plus
// register-neutral tweaks: producer-warp split (warps 0-3 fill, 4-7 pure
// consumers), kk=0 ldsm issued before the fill burst, and hoisted swizzle
// (sw128(off+kb) == sw128(off)^kb for kb in {0,32,64,96}).
// ---------------------------------------------------------------------------

static constexpr int MDIM = 16384;
static constexpr int KDIM = 4096;
static constexpr int NDIM = 4096;

static constexpr int BM = 128;
static constexpr int BN = 128;
static constexpr int BK = 32;                 // 32 tf32 = 128B row (SW128 atom)
static constexpr int STAGES = 3;
static constexpr int NKITER = KDIM / BK;      // 128
static constexpr int A_STAGE_BYTES = BM * BK * 4;   // 16384
static constexpr int B_STAGE_BYTES = BN * BK * 4;   // 16384
static constexpr int STAGE_BYTES = A_STAGE_BYTES + B_STAGE_BYTES; // 32768
static constexpr int SMEM_TOTAL = STAGES * STAGE_BYTES;           // 98304

// Device scratch (static __device__ arrays are the allowed scratch mechanism)
__device__ float g_WL[256];                           // (A@B) 16x16
__device__ float g_Wt[(size_t)NDIM * (size_t)KDIM];   // W_eff^T: [N][K], K contiguous
__device__ float g_Xc[(size_t)MDIM * (size_t)KDIM];   // tf32-rounded x

// ---------------------------------------------------------------------------
// Helpers
// ---------------------------------------------------------------------------
__device__ __forceinline__ uint32_t smem_u32(const void* p) {
    uint32_t a;
    asm("{ .reg .u64 t; cvta.to.shared.u64 t, %1; cvt.u32.u64 %0, t; }" : "=r"(a) : "l"(p));
    return a;
}

__device__ __forceinline__ float cvt_tf32(float x) {
    uint32_t o;
    asm("cvt.rna.tf32.f32 %0, %1;" : "=r"(o) : "f"(x));
    return __uint_as_float(o);
}

__device__ __forceinline__ void cp16(uint32_t saddr, const float* g) {
    asm volatile("cp.async.cg.shared.global [%0], [%1], 16;\n" :: "r"(saddr), "l"(g));
}
#define CP_COMMIT() asm volatile("cp.async.commit_group;\n" ::: "memory")

__device__ __forceinline__ void ldsm_x4(uint32_t& r0, uint32_t& r1, uint32_t& r2, uint32_t& r3,
                                        uint32_t addr) {
    asm volatile("ldmatrix.sync.aligned.m8n8.x4.shared.b16 {%0,%1,%2,%3}, [%4];\n"
                 : "=r"(r0), "=r"(r1), "=r"(r2), "=r"(r3) : "r"(addr));
}

__device__ __forceinline__ void mma_tf32(float& d0, float& d1, float& d2, float& d3,
                                         uint32_t a0, uint32_t a1, uint32_t a2, uint32_t a3,
                                         uint32_t b0, uint32_t b1) {
    asm volatile(
        "mma.sync.aligned.m16n8k8.row.col.f32.tf32.tf32.f32 "
        "{%0,%1,%2,%3}, {%4,%5,%6,%7}, {%8,%9}, {%0,%1,%2,%3};\n"
        : "+f"(d0), "+f"(d1), "+f"(d2), "+f"(d3)
        : "r"(a0), "r"(a1), "r"(a2), "r"(a3), "r"(b0), "r"(b1));
}

__device__ __forceinline__ uint32_t sw128(uint32_t off) {
    return off ^ ((off >> 3) & 0x70);
}

// ---------------------------------------------------------------------------
// Kernel 1: WL = lora_A @ lora_B (16x16)
// ---------------------------------------------------------------------------
__global__ void lokr_compute_wl(const float* __restrict__ A, const float* __restrict__ B) {
    const int i = threadIdx.x >> 4, j = threadIdx.x & 15;
    float s = 0.f;
#pragma unroll
    for (int r = 0; r < 16; r++) s += A[i * 16 + r] * B[r * 16 + j];
    g_WL[threadIdx.x] = s;
}

// ---------------------------------------------------------------------------
// Kernel 2: Wt[n][k] = round_tf32(base[k][n] + 2*WL[k/256][n/256]*O[k%256][n%256])
// (transpose through padded SMEM tiles; all global accesses coalesced)
// ---------------------------------------------------------------------------
__global__ void lokr_build_wt(const float* __restrict__ base, const float* __restrict__ O) {
    __shared__ float tb[32][33];
    __shared__ float to[32][33];
    const int k0 = blockIdx.x * 32;
    const int n0 = blockIdx.y * 32;
    const int tx = threadIdx.x, ty = threadIdx.y;
    const float wl2 = 2.0f * g_WL[(k0 >> 8) * 16 + (n0 >> 8)];
    const int p0 = k0 & 255, q0 = n0 & 255;
#pragma unroll
    for (int i = 0; i < 4; i++) {
        const int r = ty + i * 8;
        tb[r][tx] = base[(size_t)(k0 + r) * NDIM + n0 + tx];
        to[r][tx] = O[(p0 + r) * 256 + q0 + tx];
    }
    __syncthreads();
#pragma unroll
    for (int i = 0; i < 4; i++) {
        const int r = ty + i * 8;   // n-offset within tile
        g_Wt[(size_t)(n0 + r) * KDIM + k0 + tx] = cvt_tf32(tb[tx][r] + wl2 * to[tx][r]);
    }
}

// ---------------------------------------------------------------------------
// Kernel 3: Xc = round_tf32(x), vectorized
// ---------------------------------------------------------------------------
__global__ void lokr_cvt_x(const float4* __restrict__ x) {
    const size_t i = (size_t)blockIdx.x * blockDim.x + threadIdx.x;
    float4 v = x[i];
    v.x = cvt_tf32(v.x); v.y = cvt_tf32(v.y);
    v.z = cvt_tf32(v.z); v.w = cvt_tf32(v.w);
    reinterpret_cast<float4*>(g_Xc)[i] = v;
}

// ---------------------------------------------------------------------------
// Kernel 4: TF32 mma.sync GEMM. BM=128 x BN=128 x BK=32, 3-stage cp.async,
// 2 CTAs/SM. 256 threads = 8 warps; warp grid 2(m) x 4(n); warp tile 64x32.
// Fills issued by warps 0-3 only (128 producer threads, 16 cp.async each).
// ---------------------------------------------------------------------------
__device__ __forceinline__ void gemm_fill_stage_half(uint32_t smem_base, int stage, int kt,
                                                     const float* Abase, const float* Bbase,
                                                     int tid /* 0..127 */) {
    const uint32_t sa = smem_base + stage * STAGE_BYTES;
    const uint32_t sb = sa + A_STAGE_BYTES;
    const int k0 = kt * BK;
    // A: 128 rows x 8 16B-chunks = 1024 chunks; 8 per producer thread
#pragma unroll
    for (int j = 0; j < 8; j++) {
        const int c = j * 128 + tid;
        const int row = c >> 3, col4 = c & 7;
        cp16(sa + sw128((uint32_t)(row * 128 + col4 * 16)),
             Abase + (size_t)row * KDIM + k0 + col4 * 4);
    }
    // B: same shape
#pragma unroll
    for (int j = 0; j < 8; j++) {
        const int c = j * 128 + tid;
        const int row = c >> 3, col4 = c & 7;
        cp16(sb + sw128((uint32_t)(row * 128 + col4 * 16)),
             Bbase + (size_t)row * KDIM + k0 + col4 * 4);
    }
    CP_COMMIT();
}

__global__ void __launch_bounds__(256, 2)
lokr_gemm_tf32(const float* __restrict__ bias, float* __restrict__ out) {
    extern __shared__ char smem[];
    const uint32_t smem_base = smem_u32(smem);
    const int tid = threadIdx.x;
    const int lane = tid & 31, wid = tid >> 5;
    const bool producer = (tid < 128);
    const int warp_m = (wid & 1) * 64;   // 2 warps along m
    const int warp_n = (wid >> 1) * 32;  // 4 warps along n
    const int n0 = blockIdx.x * BN;
    const int m0 = blockIdx.y * BM;

    const float* Abase = g_Xc + (size_t)m0 * KDIM;
    const float* Bbase = g_Wt + (size_t)n0 * KDIM;

    // Pre-swizzled per-thread ldmatrix offsets. kb in {0,32,64,96} occupies
    // bits 5-6 (disjoint from colp bit 4; row bits >=7 unaffected), so
    // sw128(off + kb) == sw128(off) ^ kb.
    uint32_t aSw[4], bSw[2];
    {
        const uint32_t colp = ((lane >> 4) & 1) * 16;  // k-half select (16B)
#pragma unroll
        for (int i = 0; i < 4; i++)
            aSw[i] = sw128((uint32_t)((warp_m + i * 16 + (lane & 15)) * 128) + colp);
#pragma unroll
        for (int j = 0; j < 2; j++)
            bSw[j] = sw128((uint32_t)((warp_n + j * 16 + (lane & 15)) * 128) + colp);
    }

    float d[4][4][4];
#pragma unroll
    for (int i = 0; i < 4; i++)
#pragma unroll
        for (int n = 0; n < 4; n++)
#pragma unroll
            for (int c = 0; c < 4; c++) d[i][n][c] = 0.f;

    uint32_t a[4][4];
    uint32_t b[4][2];

    // Prologue: producers fill STAGES-1 stages
    if (producer) {
#pragma unroll
        for (int s = 0; s < STAGES - 1; s++)
            gemm_fill_stage_half(smem_base, s, s, Abase, Bbase, tid);
    }

    for (int kt = 0; kt < NKITER; kt++) {
        const int s = kt % STAGES;
        if (producer)
            asm volatile("cp.async.wait_group %0;\n" :: "n"(STAGES - 2) : "memory");
        __syncthreads();

        const uint32_t sa = smem_base + s * STAGE_BYTES;
        const uint32_t sb = sa + A_STAGE_BYTES;

        // kk=0 fragment loads FIRST (dependent chain starts immediately)
#pragma unroll
        for (int i = 0; i < 4; i++)
            ldsm_x4(a[i][0], a[i][1], a[i][2], a[i][3], sa + aSw[i]);
#pragma unroll
        for (int j = 0; j < 2; j++) {
            uint32_t r0, r1, r2, r3;
            ldsm_x4(r0, r1, r2, r3, sb + bSw[j]);
            b[2 * j][0] = r0; b[2 * j + 1][0] = r1;
            b[2 * j][1] = r2; b[2 * j + 1][1] = r3;
        }

        // Producers issue the next stage's fill (overlaps ldsm latency + MMAs)
        if (producer) {
            if (kt + STAGES - 1 < NKITER)
                gemm_fill_stage_half(smem_base, (kt + STAGES - 1) % STAGES, kt + STAGES - 1,
                                     Abase, Bbase, tid);
            else
                CP_COMMIT();  // empty group keeps wait_group accounting uniform
        }

#pragma unroll
        for (int kk = 0; kk < BK / 8; kk++) {
            if (kk > 0) {
                const uint32_t kb = (uint32_t)(kk * 32);
#pragma unroll
                for (int i = 0; i < 4; i++)
                    ldsm_x4(a[i][0], a[i][1], a[i][2], a[i][3], sa + (aSw[i] ^ kb));
#pragma unroll
                for (int j = 0; j < 2; j++) {
                    uint32_t r0, r1, r2, r3;
                    ldsm_x4(r0, r1, r2, r3, sb + (bSw[j] ^ kb));
                    b[2 * j][0] = r0; b[2 * j + 1][0] = r1;
                    b[2 * j][1] = r2; b[2 * j + 1][1] = r3;
                }
            }
#pragma unroll
            for (int i = 0; i < 4; i++)
#pragma unroll
                for (int n = 0; n < 4; n++)
                    mma_tf32(d[i][n][0], d[i][n][1], d[i][n][2], d[i][n][3],
                             a[i][0], a[i][1], a[i][2], a[i][3], b[n][0], b[n][1]);
        }
    }

    // Epilogue: add bias, store float2 per (row, n-block)
#pragma unroll
    for (int i = 0; i < 4; i++) {
        const int row = m0 + warp_m + i * 16 + (lane >> 2);
#pragma unroll
        for (int n = 0; n < 4; n++) {
            const int col = n0 + warp_n + n * 8 + (lane & 3) * 2;
            const float bv0 = bias[col], bv1 = bias[col + 1];
            float2 v0 = make_float2(d[i][n][0] + bv0, d[i][n][1] + bv1);
            float2 v1 = make_float2(d[i][n][2] + bv0, d[i][n][3] + bv1);
            *reinterpret_cast<float2*>(out + (size_t)row * NDIM + col) = v0;
            *reinterpret_cast<float2*>(out + (size_t)(row + 8) * NDIM + col) = v1;
        }
    }
}

// ---------------------------------------------------------------------------
// Launch
// ---------------------------------------------------------------------------
extern "C" void kernel_launch(void* const* d_in, const int* in_sizes, int n_in,
                              void* d_out, int out_size) {
    (void)in_sizes; (void)n_in; (void)out_size;
    const float* x    = (const float*)d_in[0];
    const float* base = (const float*)d_in[1];
    const float* bias = (const float*)d_in[2];
    const float* la   = (const float*)d_in[3];
    const float* lb   = (const float*)d_in[4];
    const float* O    = (const float*)d_in[5];
    float* out = (float*)d_out;

    lokr_compute_wl<<<1, 256>>>(la, lb);

    dim3 gw(KDIM / 32, NDIM / 32);
    lokr_build_wt<<<gw, dim3(32, 8)>>>(base, O);

    const size_t n4 = (size_t)MDIM * KDIM / 4;   // 16M float4
    lokr_cvt_x<<<(unsigned)(n4 / 256), 256>>>((const float4*)x);

    cudaFuncSetAttribute(lokr_gemm_tf32, cudaFuncAttributeMaxDynamicSharedMemorySize, SMEM_TOTAL);
    dim3 gg(NDIM / BN, MDIM / BM);
    lokr_gemm_tf32<<<gg, 256, SMEM_TOTAL>>>(bias, out);
}

// round 11
// speedup vs baseline: 1.1340x; 1.0632x over previous
#include <cuda_runtime.h>
#include <cstdint>

// ---------------------------------------------------------------------------
// LokrLinear: out = x @ (base_kernel + 2.0 * kron(lora_A@lora_B, O)) + bias
//
// Base-ISA path (tcgen05 is 'a'-gated; harness builds compute_103 PTX):
//   1) WL = lora_A @ lora_B (16x16)
//   2) Wt[n][k] = round_tf32(base[k][n] + 2*WL[k/256][n/256]*O[k%256][n%256])
//   3) Xc = round_tf32(x)            (RNA rounding avoids HMMA truncation bias)
//   4) out = Xc @ Wt^T + bias via mma.sync.m16n8k8.tf32, cp.async 3-stage
//      pipeline, SW128-swizzled smem, ldmatrix fragment loads.
//
// R10: exact R5 config (128x128 block, 64x32 warp tile, occ 2, symmetric
// fill — best so far at 2722us) plus two register-neutral micro-changes:
//   (a) hoisted swizzle: sw128(off+kb) == sw128(off)^kb, kb in {0,32,64,96}
//   (b) fill smoothing: the 8-cp.async-per-thread stage fill is spread
//       1 A-chunk + 1 B-chunk per kk-step (after ldsm, before MMAs), so LSU
//       issue interleaves with tensor work instead of bursting post-barrier.
// ---------------------------------------------------------------------------

static constexpr int MDIM = 16384;
static constexpr int KDIM = 4096;
static constexpr int NDIM = 4096;

static constexpr int BM = 128;
static constexpr int BN = 128;
static constexpr int BK = 32;                 // 32 tf32 = 128B row (SW128 atom)
static constexpr int STAGES = 3;
static constexpr int NKITER = KDIM / BK;      // 128
static constexpr int A_STAGE_BYTES = BM * BK * 4;   // 16384
static constexpr int B_STAGE_BYTES = BN * BK * 4;   // 16384
static constexpr int STAGE_BYTES = A_STAGE_BYTES + B_STAGE_BYTES; // 32768
static constexpr int SMEM_TOTAL = STAGES * STAGE_BYTES;           // 98304

// Device scratch (static __device__ arrays are the allowed scratch mechanism)
__device__ float g_WL[256];                           // (A@B) 16x16
__device__ float g_Wt[(size_t)NDIM * (size_t)KDIM];   // W_eff^T: [N][K], K contiguous
__device__ float g_Xc[(size_t)MDIM * (size_t)KDIM];   // tf32-rounded x

// ---------------------------------------------------------------------------
// Helpers
// ---------------------------------------------------------------------------
__device__ __forceinline__ uint32_t smem_u32(const void* p) {
    uint32_t a;
    asm("{ .reg .u64 t; cvta.to.shared.u64 t, %1; cvt.u32.u64 %0, t; }" : "=r"(a) : "l"(p));
    return a;
}

__device__ __forceinline__ float cvt_tf32(float x) {
    uint32_t o;
    asm("cvt.rna.tf32.f32 %0, %1;" : "=r"(o) : "f"(x));
    return __uint_as_float(o);
}

__device__ __forceinline__ void cp16(uint32_t saddr, const float* g) {
    asm volatile("cp.async.cg.shared.global [%0], [%1], 16;\n" :: "r"(saddr), "l"(g));
}
#define CP_COMMIT() asm volatile("cp.async.commit_group;\n" ::: "memory")

__device__ __forceinline__ void ldsm_x4(uint32_t& r0, uint32_t& r1, uint32_t& r2, uint32_t& r3,
                                        uint32_t addr) {
    asm volatile("ldmatrix.sync.aligned.m8n8.x4.shared.b16 {%0,%1,%2,%3}, [%4];\n"
                 : "=r"(r0), "=r"(r1), "=r"(r2), "=r"(r3) : "r"(addr));
}

__device__ __forceinline__ void mma_tf32(float& d0, float& d1, float& d2, float& d3,
                                         uint32_t a0, uint32_t a1, uint32_t a2, uint32_t a3,
                                         uint32_t b0, uint32_t b1) {
    asm volatile(
        "mma.sync.aligned.m16n8k8.row.col.f32.tf32.tf32.f32 "
        "{%0,%1,%2,%3}, {%4,%5,%6,%7}, {%8,%9}, {%0,%1,%2,%3};\n"
        : "+f"(d0), "+f"(d1), "+f"(d2), "+f"(d3)
        : "r"(a0), "r"(a1), "r"(a2), "r"(a3), "r"(b0), "r"(b1));
}

__device__ __forceinline__ uint32_t sw128(uint32_t off) {
    return off ^ ((off >> 3) & 0x70);
}

// ---------------------------------------------------------------------------
// Kernel 1: WL = lora_A @ lora_B (16x16)
// ---------------------------------------------------------------------------
__global__ void lokr_compute_wl(const float* __restrict__ A, const float* __restrict__ B) {
    const int i = threadIdx.x >> 4, j = threadIdx.x & 15;
    float s = 0.f;
#pragma unroll
    for (int r = 0; r < 16; r++) s += A[i * 16 + r] * B[r * 16 + j];
    g_WL[threadIdx.x] = s;
}

// ---------------------------------------------------------------------------
// Kernel 2: Wt[n][k] = round_tf32(base[k][n] + 2*WL[k/256][n/256]*O[k%256][n%256])
// (transpose through padded SMEM tiles; all global accesses coalesced)
// ---------------------------------------------------------------------------
__global__ void lokr_build_wt(const float* __restrict__ base, const float* __restrict__ O) {
    __shared__ float tb[32][33];
    __shared__ float to[32][33];
    const int k0 = blockIdx.x * 32;
    const int n0 = blockIdx.y * 32;
    const int tx = threadIdx.x, ty = threadIdx.y;
    const float wl2 = 2.0f * g_WL[(k0 >> 8) * 16 + (n0 >> 8)];
    const int p0 = k0 & 255, q0 = n0 & 255;
#pragma unroll
    for (int i = 0; i < 4; i++) {
        const int r = ty + i * 8;
        tb[r][tx] = base[(size_t)(k0 + r) * NDIM + n0 + tx];
        to[r][tx] = O[(p0 + r) * 256 + q0 + tx];
    }
    __syncthreads();
#pragma unroll
    for (int i = 0; i < 4; i++) {
        const int r = ty + i * 8;   // n-offset within tile
        g_Wt[(size_t)(n0 + r) * KDIM + k0 + tx] = cvt_tf32(tb[tx][r] + wl2 * to[tx][r]);
    }
}

// ---------------------------------------------------------------------------
// Kernel 3: Xc = round_tf32(x), vectorized
// ---------------------------------------------------------------------------
__global__ void lokr_cvt_x(const float4* __restrict__ x) {
    const size_t i = (size_t)blockIdx.x * blockDim.x + threadIdx.x;
    float4 v = x[i];
    v.x = cvt_tf32(v.x); v.y = cvt_tf32(v.y);
    v.z = cvt_tf32(v.z); v.w = cvt_tf32(v.w);
    reinterpret_cast<float4*>(g_Xc)[i] = v;
}

// ---------------------------------------------------------------------------
// Kernel 4: TF32 mma.sync GEMM. BM=128 x BN=128 x BK=32, 3-stage cp.async,
// 2 CTAs/SM. 256 threads = 8 warps; warp grid 2(m) x 4(n); warp tile 64x32.
// Stage fill spread across the 4 kk-steps (1 A-chunk + 1 B-chunk per step).
// ---------------------------------------------------------------------------
__device__ __forceinline__ void gemm_fill_part(uint32_t smem_base, int stage, int kt,
                                               int part /*0..3*/, int tid) {
    // part p covers A chunks c = p*256 + tid and B chunks likewise.
    const uint32_t sa = smem_base + stage * STAGE_BYTES;
    const uint32_t sb = sa + A_STAGE_BYTES;
    const int k0 = kt * BK;
    const int c = part * 256 + tid;
    const int row = c >> 3, col4 = c & 7;
    const uint32_t so = sw128((uint32_t)(row * 128 + col4 * 16));
    const size_t go = (size_t)row * KDIM + k0 + col4 * 4;
    cp16(sa + so, g_Xc + go);   // overwritten below by caller-provided bases
}

__global__ void __launch_bounds__(256, 2)
lokr_gemm_tf32(const float* __restrict__ bias, float* __restrict__ out) {
    extern __shared__ char smem[];
    const uint32_t smem_base = smem_u32(smem);
    const int tid = threadIdx.x;
    const int lane = tid & 31, wid = tid >> 5;
    const int warp_m = (wid & 1) * 64;   // 2 warps along m
    const int warp_n = (wid >> 1) * 32;  // 4 warps along n
    const int n0 = blockIdx.x * BN;
    const int m0 = blockIdx.y * BM;

    const float* Abase = g_Xc + (size_t)m0 * KDIM;
    const float* Bbase = g_Wt + (size_t)n0 * KDIM;

    // Per-thread fill addressing (fixed across iterations except k0 / stage).
    const int frow = tid >> 3, fcol4 = tid & 7;               // part stride = 32 rows
    const uint32_t fsw = sw128((uint32_t)(frow * 128 + fcol4 * 16));
    // part p: row = frow + p*32  -> smem off = fsw + p*32*128 (bits >=12, swizzle-safe)

    // Pre-swizzled ldmatrix offsets; kb in {0,32,64,96} toggles bits 5-6 only,
    // so sw128(off + kb) == sw128(off) ^ kb.
    uint32_t aSw[4], bSw[2];
    {
        const uint32_t colp = ((lane >> 4) & 1) * 16;  // k-half select (16B)
#pragma unroll
        for (int i = 0; i < 4; i++)
            aSw[i] = sw128((uint32_t)((warp_m + i * 16 + (lane & 15)) * 128) + colp);
#pragma unroll
        for (int j = 0; j < 2; j++)
            bSw[j] = sw128((uint32_t)((warp_n + j * 16 + (lane & 15)) * 128) + colp);
    }

    float d[4][4][4];
#pragma unroll
    for (int i = 0; i < 4; i++)
#pragma unroll
        for (int n = 0; n < 4; n++)
#pragma unroll
            for (int c = 0; c < 4; c++) d[i][n][c] = 0.f;

    uint32_t a[4][4];
    uint32_t b[4][2];

    // Prologue: fill STAGES-1 stages (full burst is fine here; nothing to overlap)
#pragma unroll
    for (int s = 0; s < STAGES - 1; s++) {
        const uint32_t sa = smem_base + s * STAGE_BYTES;
        const uint32_t sb = sa + A_STAGE_BYTES;
        const int k0 = s * BK;
#pragma unroll
        for (int p = 0; p < 4; p++) {
            const uint32_t so = fsw + (uint32_t)(p * 32 * 128);
            const size_t go = (size_t)(frow + p * 32) * KDIM + k0 + fcol4 * 4;
            cp16(sa + so, Abase + go);
            cp16(sb + so, Bbase + go);
        }
        CP_COMMIT();
    }

    for (int kt = 0; kt < NKITER; kt++) {
        const int s = kt % STAGES;
        asm volatile("cp.async.wait_group %0;\n" :: "n"(STAGES - 2) : "memory");
        __syncthreads();

        const uint32_t sa = smem_base + s * STAGE_BYTES;
        const uint32_t sb = sa + A_STAGE_BYTES;

        const bool do_fill = (kt + STAGES - 1 < NKITER);
        const int fs = (kt + STAGES - 1) % STAGES;
        const uint32_t fa = smem_base + fs * STAGE_BYTES;
        const uint32_t fb = fa + A_STAGE_BYTES;
        const int fk0 = (kt + STAGES - 1) * BK;

#pragma unroll
        for (int kk = 0; kk < BK / 8; kk++) {
            const uint32_t kb = (uint32_t)(kk * 32);
            // Fragment loads for this kk (dependent chain first)
#pragma unroll
            for (int i = 0; i < 4; i++)
                ldsm_x4(a[i][0], a[i][1], a[i][2], a[i][3], sa + (aSw[i] ^ kb));
#pragma unroll
            for (int j = 0; j < 2; j++) {
                uint32_t r0, r1, r2, r3;
                ldsm_x4(r0, r1, r2, r3, sb + (bSw[j] ^ kb));
                b[2 * j][0] = r0; b[2 * j + 1][0] = r1;
                b[2 * j][1] = r2; b[2 * j + 1][1] = r3;
            }
            // One A-chunk + one B-chunk of the next stage's fill (smooth LSU)
            if (do_fill) {
                const uint32_t so = fsw + (uint32_t)(kk * 32 * 128);
                const size_t go = (size_t)(frow + kk * 32) * KDIM + fk0 + fcol4 * 4;
                cp16(fa + so, Abase + go);
                cp16(fb + so, Bbase + go);
            }
            // 16 MMAs on this kk's fragments (ldsm/cp latency drains underneath)
#pragma unroll
            for (int i = 0; i < 4; i++)
#pragma unroll
                for (int n = 0; n < 4; n++)
                    mma_tf32(d[i][n][0], d[i][n][1], d[i][n][2], d[i][n][3],
                             a[i][0], a[i][1], a[i][2], a[i][3], b[n][0], b[n][1]);
        }
        CP_COMMIT();  // one group per k-iter (empty when !do_fill) keeps accounting uniform
    }

    // Epilogue: add bias, store float2 per (row, n-block)
#pragma unroll
    for (int i = 0; i < 4; i++) {
        const int row = m0 + warp_m + i * 16 + (lane >> 2);
#pragma unroll
        for (int n = 0; n < 4; n++) {
            const int col = n0 + warp_n + n * 8 + (lane & 3) * 2;
            const float bv0 = bias[col], bv1 = bias[col + 1];
            float2 v0 = make_float2(d[i][n][0] + bv0, d[i][n][1] + bv1);
            float2 v1 = make_float2(d[i][n][2] + bv0, d[i][n][3] + bv1);
            *reinterpret_cast<float2*>(out + (size_t)row * NDIM + col) = v0;
            *reinterpret_cast<float2*>(out + (size_t)(row + 8) * NDIM + col) = v1;
        }
    }
}

// ---------------------------------------------------------------------------
// Launch
// ---------------------------------------------------------------------------
extern "C" void kernel_launch(void* const* d_in, const int* in_sizes, int n_in,
                              void* d_out, int out_size) {
    (void)in_sizes; (void)n_in; (void)out_size;
    const float* x    = (const float*)d_in[0];
    const float* base = (const float*)d_in[1];
    const float* bias = (const float*)d_in[2];
    const float* la   = (const float*)d_in[3];
    const float* lb   = (const float*)d_in[4];
    const float* O    = (const float*)d_in[5];
    float* out = (float*)d_out;

    lokr_compute_wl<<<1, 256>>>(la, lb);

    dim3 gw(KDIM / 32, NDIM / 32);
    lokr_build_wt<<<gw, dim3(32, 8)>>>(base, O);

    const size_t n4 = (size_t)MDIM * KDIM / 4;   // 16M float4
    lokr_cvt_x<<<(unsigned)(n4 / 256), 256>>>((const float4*)x);

    cudaFuncSetAttribute(lokr_gemm_tf32, cudaFuncAttributeMaxDynamicSharedMemorySize, SMEM_TOTAL);
    dim3 gg(NDIM / BN, MDIM / BM);
    lokr_gemm_tf32<<<gg, 256, SMEM_TOTAL>>>(bias, out);
}

// round 13
// speedup vs baseline: 1.1719x; 1.0334x over previous
#include <cuda_runtime.h>
#include <cstdint>

// ---------------------------------------------------------------------------
// LokrLinear: out = x @ (base_kernel + 2.0 * kron(lora_A@lora_B, O)) + bias
//
// Base-ISA path (tcgen05 is 'a'-gated; harness builds compute_103 PTX):
//   1) WL = lora_A @ lora_B (16x16)
//   2) Wt[n][k] = round_tf32(base[k][n] + 2*WL[k/256][n/256]*O[k%256][n%256])
//   3) Xc = round_tf32(x)            (RNA rounding avoids HMMA truncation bias)
//   4) out = Xc @ Wt^T + bias via mma.sync.m16n8k8.tf32, cp.async 3-stage
//      pipeline, SW128-swizzled smem, ldmatrix fragment loads.
//
// R11: R10 config (best: 2691us) with the k-loop unrolled by 3 so all stage
// bases are compile-time constants (no modulo / stage-pointer math), fill
// gmem addressing reduced to two running pointers (+BK per iter), and B-then-A
// ldsm ordering so the first MMA's operands arrive after 3 ldsm, not 6.
// ---------------------------------------------------------------------------

static constexpr int MDIM = 16384;
static constexpr int KDIM = 4096;
static constexpr int NDIM = 4096;

static constexpr int BM = 128;
static constexpr int BN = 128;
static constexpr int BK = 32;                 // 32 tf32 = 128B row (SW128 atom)
static constexpr int STAGES = 3;
static constexpr int NKITER = KDIM / BK;      // 128
static constexpr int A_STAGE_BYTES = BM * BK * 4;   // 16384
static constexpr int B_STAGE_BYTES = BN * BK * 4;   // 16384
static constexpr int STAGE_BYTES = A_STAGE_BYTES + B_STAGE_BYTES; // 32768
static constexpr int SMEM_TOTAL = STAGES * STAGE_BYTES;           // 98304

// Device scratch (static __device__ arrays are the allowed scratch mechanism)
__device__ float g_WL[256];                           // (A@B) 16x16
__device__ float g_Wt[(size_t)NDIM * (size_t)KDIM];   // W_eff^T: [N][K], K contiguous
__device__ float g_Xc[(size_t)MDIM * (size_t)KDIM];   // tf32-rounded x

// ---------------------------------------------------------------------------
// Helpers
// ---------------------------------------------------------------------------
__device__ __forceinline__ uint32_t smem_u32(const void* p) {
    uint32_t a;
    asm("{ .reg .u64 t; cvta.to.shared.u64 t, %1; cvt.u32.u64 %0, t; }" : "=r"(a) : "l"(p));
    return a;
}

__device__ __forceinline__ float cvt_tf32(float x) {
    uint32_t o;
    asm("cvt.rna.tf32.f32 %0, %1;" : "=r"(o) : "f"(x));
    return __uint_as_float(o);
}

__device__ __forceinline__ void cp16(uint32_t saddr, const float* g) {
    asm volatile("cp.async.cg.shared.global [%0], [%1], 16;\n" :: "r"(saddr), "l"(g));
}
#define CP_COMMIT() asm volatile("cp.async.commit_group;\n" ::: "memory")

__device__ __forceinline__ void ldsm_x4(uint32_t& r0, uint32_t& r1, uint32_t& r2, uint32_t& r3,
                                        uint32_t addr) {
    asm volatile("ldmatrix.sync.aligned.m8n8.x4.shared.b16 {%0,%1,%2,%3}, [%4];\n"
                 : "=r"(r0), "=r"(r1), "=r"(r2), "=r"(r3) : "r"(addr));
}

__device__ __forceinline__ void mma_tf32(float& d0, float& d1, float& d2, float& d3,
                                         uint32_t a0, uint32_t a1, uint32_t a2, uint32_t a3,
                                         uint32_t b0, uint32_t b1) {
    asm volatile(
        "mma.sync.aligned.m16n8k8.row.col.f32.tf32.tf32.f32 "
        "{%0,%1,%2,%3}, {%4,%5,%6,%7}, {%8,%9}, {%0,%1,%2,%3};\n"
        : "+f"(d0), "+f"(d1), "+f"(d2), "+f"(d3)
        : "r"(a0), "r"(a1), "r"(a2), "r"(a3), "r"(b0), "r"(b1));
}

__device__ __forceinline__ uint32_t sw128(uint32_t off) {
    return off ^ ((off >> 3) & 0x70);
}

// ---------------------------------------------------------------------------
// Kernel 1: WL = lora_A @ lora_B (16x16)
// ---------------------------------------------------------------------------
__global__ void lokr_compute_wl(const float* __restrict__ A, const float* __restrict__ B) {
    const int i = threadIdx.x >> 4, j = threadIdx.x & 15;
    float s = 0.f;
#pragma unroll
    for (int r = 0; r < 16; r++) s += A[i * 16 + r] * B[r * 16 + j];
    g_WL[threadIdx.x] = s;
}

// ---------------------------------------------------------------------------
// Kernel 2: Wt[n][k] = round_tf32(base[k][n] + 2*WL[k/256][n/256]*O[k%256][n%256])
// (transpose through padded SMEM tiles; all global accesses coalesced)
// ---------------------------------------------------------------------------
__global__ void lokr_build_wt(const float* __restrict__ base, const float* __restrict__ O) {
    __shared__ float tb[32][33];
    __shared__ float to[32][33];
    const int k0 = blockIdx.x * 32;
    const int n0 = blockIdx.y * 32;
    const int tx = threadIdx.x, ty = threadIdx.y;
    const float wl2 = 2.0f * g_WL[(k0 >> 8) * 16 + (n0 >> 8)];
    const int p0 = k0 & 255, q0 = n0 & 255;
#pragma unroll
    for (int i = 0; i < 4; i++) {
        const int r = ty + i * 8;
        tb[r][tx] = base[(size_t)(k0 + r) * NDIM + n0 + tx];
        to[r][tx] = O[(p0 + r) * 256 + q0 + tx];
    }
    __syncthreads();
#pragma unroll
    for (int i = 0; i < 4; i++) {
        const int r = ty + i * 8;   // n-offset within tile
        g_Wt[(size_t)(n0 + r) * KDIM + k0 + tx] = cvt_tf32(tb[tx][r] + wl2 * to[tx][r]);
    }
}

// ---------------------------------------------------------------------------
// Kernel 3: Xc = round_tf32(x), vectorized
// ---------------------------------------------------------------------------
__global__ void lokr_cvt_x(const float4* __restrict__ x) {
    const size_t i = (size_t)blockIdx.x * blockDim.x + threadIdx.x;
    float4 v = x[i];
    v.x = cvt_tf32(v.x); v.y = cvt_tf32(v.y);
    v.z = cvt_tf32(v.z); v.w = cvt_tf32(v.w);
    reinterpret_cast<float4*>(g_Xc)[i] = v;
}

// ---------------------------------------------------------------------------
// Kernel 4: TF32 mma.sync GEMM. BM=128 x BN=128 x BK=32, 3-stage cp.async,
// 2 CTAs/SM. 256 threads = 8 warps; warp grid 2(m) x 4(n); warp tile 64x32.
// k-loop unrolled by 3: stage bases are compile-time constants.
// ---------------------------------------------------------------------------
struct KIterState {
    const float* pAf;   // running fill pointer (A), advances +BK per iter
    const float* pBf;   // running fill pointer (B)
    uint32_t fsw;       // per-thread swizzled fill offset within a stage
    uint32_t aSw[4];    // pre-swizzled ldsm offsets (A)
    uint32_t bSw[2];    // pre-swizzled ldsm offsets (B)
};

// One k-iteration. sa/fa are compile-time-constant stage bases at call sites.
__device__ __forceinline__ void k_iter(uint32_t sa, uint32_t fa, bool doFill,
                                       KIterState& st, float d[4][4][4]) {
    asm volatile("cp.async.wait_group 1;\n" ::: "memory");
    __syncthreads();
    const uint32_t sb = sa + A_STAGE_BYTES;
    const uint32_t fb = fa + A_STAGE_BYTES;

    uint32_t a[4][4];
    uint32_t b[4][2];

#pragma unroll
    for (int kk = 0; kk < BK / 8; kk++) {
        const uint32_t kb = (uint32_t)(kk * 32);
        // B fragments first: first MMA's operands ready after 3 ldsm, not 6.
#pragma unroll
        for (int j = 0; j < 2; j++) {
            uint32_t r0, r1, r2, r3;
            ldsm_x4(r0, r1, r2, r3, sb + (st.bSw[j] ^ kb));
            b[2 * j][0] = r0; b[2 * j + 1][0] = r1;
            b[2 * j][1] = r2; b[2 * j + 1][1] = r3;
        }
#pragma unroll
        for (int i = 0; i < 4; i++)
            ldsm_x4(a[i][0], a[i][1], a[i][2], a[i][3], sa + (st.aSw[i] ^ kb));

        // One A-chunk + one B-chunk of the next stage's fill (smooth LSU issue)
        if (doFill) {
            const uint32_t so = st.fsw + (uint32_t)(kk * 32 * 128);
            const size_t go = (size_t)kk * 32 * KDIM;
            cp16(fa + so, st.pAf + go);
            cp16(fb + so, st.pBf + go);
        }

        // 16 MMAs on this kk's fragments
#pragma unroll
        for (int i = 0; i < 4; i++)
#pragma unroll
            for (int n = 0; n < 4; n++)
                mma_tf32(d[i][n][0], d[i][n][1], d[i][n][2], d[i][n][3],
                         a[i][0], a[i][1], a[i][2], a[i][3], b[n][0], b[n][1]);
    }
    CP_COMMIT();   // one group per k-iter (possibly empty) keeps accounting uniform
    st.pAf += BK;
    st.pBf += BK;
}

__global__ void __launch_bounds__(256, 2)
lokr_gemm_tf32(const float* __restrict__ bias, float* __restrict__ out) {
    extern __shared__ char smem[];
    const uint32_t smem_base = smem_u32(smem);
    const int tid = threadIdx.x;
    const int lane = tid & 31, wid = tid >> 5;
    const int warp_m = (wid & 1) * 64;   // 2 warps along m
    const int warp_n = (wid >> 1) * 32;  // 4 warps along n
    const int n0 = blockIdx.x * BN;
    const int m0 = blockIdx.y * BM;

    const float* Abase = g_Xc + (size_t)m0 * KDIM;
    const float* Bbase = g_Wt + (size_t)n0 * KDIM;

    // Per-thread fill addressing: chunk c = p*256 + tid -> row = p*32 + (tid>>3),
    // col4 = tid&7. Stage-local swizzled offset for p=0; p adds 4096 bytes
    // (bits >=12, swizzle-invariant).
    const int frow = tid >> 3, fcol4 = tid & 7;
    KIterState st;
    st.fsw = sw128((uint32_t)(frow * 128 + fcol4 * 16));

    // Pre-swizzled ldmatrix offsets; kb in {0,32,64,96} toggles bits 5-6 only,
    // so sw128(off + kb) == sw128(off) ^ kb.
    {
        const uint32_t colp = ((lane >> 4) & 1) * 16;  // k-half select (16B)
#pragma unroll
        for (int i = 0; i < 4; i++)
            st.aSw[i] = sw128((uint32_t)((warp_m + i * 16 + (lane & 15)) * 128) + colp);
#pragma unroll
        for (int j = 0; j < 2; j++)
            st.bSw[j] = sw128((uint32_t)((warp_n + j * 16 + (lane & 15)) * 128) + colp);
    }

    const float* pA0 = Abase + (size_t)frow * KDIM + fcol4 * 4;
    const float* pB0 = Bbase + (size_t)frow * KDIM + fcol4 * 4;

    float d[4][4][4];
#pragma unroll
    for (int i = 0; i < 4; i++)
#pragma unroll
        for (int n = 0; n < 4; n++)
#pragma unroll
            for (int c = 0; c < 4; c++) d[i][n][c] = 0.f;

    // Prologue: fill stages 0 (k=0) and 1 (k=BK)
#pragma unroll
    for (int s = 0; s < STAGES - 1; s++) {
        const uint32_t sa = smem_base + s * STAGE_BYTES;
        const uint32_t sb = sa + A_STAGE_BYTES;
#pragma unroll
        for (int p = 0; p < 4; p++) {
            const uint32_t so = st.fsw + (uint32_t)(p * 32 * 128);
            const size_t go = (size_t)p * 32 * KDIM + s * BK;
            cp16(sa + so, pA0 + go);
            cp16(sb + so, pB0 + go);
        }
        CP_COMMIT();
    }
    st.pAf = pA0 + (STAGES - 1) * BK;   // first in-loop fill targets k-iter 2
    st.pBf = pB0 + (STAGES - 1) * BK;

    const uint32_t S0 = smem_base;
    const uint32_t S1 = smem_base + STAGE_BYTES;
    const uint32_t S2 = smem_base + 2 * STAGE_BYTES;

    // 126 = 3*42 iterations with compile-time stage bases, then 2 tail iters.
    // Iteration kt consumes stage kt%3 and fills stage (kt+2)%3.
#pragma unroll 1
    for (int t = 0; t < (NKITER - 2) / 3; t++) {
        k_iter(S0, S2, true, st, d);
        k_iter(S1, S0, true, st, d);
        k_iter(S2, S1, true, st, d);
    }
    k_iter(S0, S2, false, st, d);   // kt = 126
    k_iter(S1, S0, false, st, d);   // kt = 127

    // Epilogue: add bias, store float2 per (row, n-block)
#pragma unroll
    for (int i = 0; i < 4; i++) {
        const int row = m0 + warp_m + i * 16 + (lane >> 2);
#pragma unroll
        for (int n = 0; n < 4; n++) {
            const int col = n0 + warp_n + n * 8 + (lane & 3) * 2;
            const float bv0 = bias[col], bv1 = bias[col + 1];
            float2 v0 = make_float2(d[i][n][0] + bv0, d[i][n][1] + bv1);
            float2 v1 = make_float2(d[i][n][2] + bv0, d[i][n][3] + bv1);
            *reinterpret_cast<float2*>(out + (size_t)row * NDIM + col) = v0;
            *reinterpret_cast<float2*>(out + (size_t)(row + 8) * NDIM + col) = v1;
        }
    }
}

// ---------------------------------------------------------------------------
// Launch
// ---------------------------------------------------------------------------
extern "C" void kernel_launch(void* const* d_in, const int* in_sizes, int n_in,
                              void* d_out, int out_size) {
    (void)in_sizes; (void)n_in; (void)out_size;
    const float* x    = (const float*)d_in[0];
    const float* base = (const float*)d_in[1];
    const float* bias = (const float*)d_in[2];
    const float* la   = (const float*)d_in[3];
    const float* lb   = (const float*)d_in[4];
    const float* O    = (const float*)d_in[5];
    float* out = (float*)d_out;

    lokr_compute_wl<<<1, 256>>>(la, lb);

    dim3 gw(KDIM / 32, NDIM / 32);
    lokr_build_wt<<<gw, dim3(32, 8)>>>(base, O);

    const size_t n4 = (size_t)MDIM * KDIM / 4;   // 16M float4
    lokr_cvt_x<<<(unsigned)(n4 / 256), 256>>>((const float4*)x);

    cudaFuncSetAttribute(lokr_gemm_tf32, cudaFuncAttributeMaxDynamicSharedMemorySize, SMEM_TOTAL);
    dim3 gg(NDIM / BN, MDIM / BM);
    lokr_gemm_tf32<<<gg, 256, SMEM_TOTAL>>>(bias, out);
}

// round 14
// speedup vs baseline: 1.2721x; 1.0855x over previous
#include <cuda_runtime.h>
#include <cstdint>

// ---------------------------------------------------------------------------
// LokrLinear: out = x @ (base_kernel + 2.0 * kron(lora_A@lora_B, O)) + bias
//
// Base-ISA path (tcgen05 is 'a'-gated; harness builds compute_103 PTX):
//   1) WL = lora_A @ lora_B (16x16)
//   2) Wt[n][k] = round_tf32(base[k][n] + 2*WL[k/256][n/256]*O[k%256][n%256])
//   3) Xc = round_tf32(x)            (RNA rounding avoids HMMA truncation bias)
//   4) out = Xc @ Wt^T + bias via mma.sync.m16n8k8.tf32, cp.async 3-stage
//      pipeline, SW128-swizzled smem, ldmatrix fragment loads.
//
// R13: 128-thread CTAs, BM=64 x BN=128, warp tile 32x64 (keeps the 16 MMA per
// 6 ldsm ratio), 3 CTAs/SM. Smaller barrier domains (4 warps) x 3 independent
// CTAs per SM cover the correlated wait_group+syncthreads bubble, and the
// 170-reg budget gives ptxas slack to pipeline ldsm (128-reg cap removed).
// k-loop stays unrolled by 3 with compile-time stage bases + running fill ptrs.
// ---------------------------------------------------------------------------

static constexpr int MDIM = 16384;
static constexpr int KDIM = 4096;
static constexpr int NDIM = 4096;

static constexpr int BM = 64;
static constexpr int BN = 128;
static constexpr int BK = 32;                 // 32 tf32 = 128B row (SW128 atom)
static constexpr int STAGES = 3;
static constexpr int NKITER = KDIM / BK;      // 128
static constexpr int A_STAGE_BYTES = BM * BK * 4;   // 8192
static constexpr int B_STAGE_BYTES = BN * BK * 4;   // 16384
static constexpr int STAGE_BYTES = A_STAGE_BYTES + B_STAGE_BYTES; // 24576
static constexpr int SMEM_TOTAL = STAGES * STAGE_BYTES;           // 73728

// Device scratch (static __device__ arrays are the allowed scratch mechanism)
__device__ float g_WL[256];                           // (A@B) 16x16
__device__ float g_Wt[(size_t)NDIM * (size_t)KDIM];   // W_eff^T: [N][K], K contiguous
__device__ float g_Xc[(size_t)MDIM * (size_t)KDIM];   // tf32-rounded x

// ---------------------------------------------------------------------------
// Helpers
// ---------------------------------------------------------------------------
__device__ __forceinline__ uint32_t smem_u32(const void* p) {
    uint32_t a;
    asm("{ .reg .u64 t; cvta.to.shared.u64 t, %1; cvt.u32.u64 %0, t; }" : "=r"(a) : "l"(p));
    return a;
}

__device__ __forceinline__ float cvt_tf32(float x) {
    uint32_t o;
    asm("cvt.rna.tf32.f32 %0, %1;" : "=r"(o) : "f"(x));
    return __uint_as_float(o);
}

__device__ __forceinline__ void cp16(uint32_t saddr, const float* g) {
    asm volatile("cp.async.cg.shared.global [%0], [%1], 16;\n" :: "r"(saddr), "l"(g));
}
#define CP_COMMIT() asm volatile("cp.async.commit_group;\n" ::: "memory")

__device__ __forceinline__ void ldsm_x4(uint32_t& r0, uint32_t& r1, uint32_t& r2, uint32_t& r3,
                                        uint32_t addr) {
    asm volatile("ldmatrix.sync.aligned.m8n8.x4.shared.b16 {%0,%1,%2,%3}, [%4];\n"
                 : "=r"(r0), "=r"(r1), "=r"(r2), "=r"(r3) : "r"(addr));
}

__device__ __forceinline__ void mma_tf32(float& d0, float& d1, float& d2, float& d3,
                                         uint32_t a0, uint32_t a1, uint32_t a2, uint32_t a3,
                                         uint32_t b0, uint32_t b1) {
    asm volatile(
        "mma.sync.aligned.m16n8k8.row.col.f32.tf32.tf32.f32 "
        "{%0,%1,%2,%3}, {%4,%5,%6,%7}, {%8,%9}, {%0,%1,%2,%3};\n"
        : "+f"(d0), "+f"(d1), "+f"(d2), "+f"(d3)
        : "r"(a0), "r"(a1), "r"(a2), "r"(a3), "r"(b0), "r"(b1));
}

__device__ __forceinline__ uint32_t sw128(uint32_t off) {
    return off ^ ((off >> 3) & 0x70);
}

// ---------------------------------------------------------------------------
// Kernel 1: WL = lora_A @ lora_B (16x16)
// ---------------------------------------------------------------------------
__global__ void lokr_compute_wl(const float* __restrict__ A, const float* __restrict__ B) {
    const int i = threadIdx.x >> 4, j = threadIdx.x & 15;
    float s = 0.f;
#pragma unroll
    for (int r = 0; r < 16; r++) s += A[i * 16 + r] * B[r * 16 + j];
    g_WL[threadIdx.x] = s;
}

// ---------------------------------------------------------------------------
// Kernel 2: Wt[n][k] = round_tf32(base[k][n] + 2*WL[k/256][n/256]*O[k%256][n%256])
// (transpose through padded SMEM tiles; all global accesses coalesced)
// ---------------------------------------------------------------------------
__global__ void lokr_build_wt(const float* __restrict__ base, const float* __restrict__ O) {
    __shared__ float tb[32][33];
    __shared__ float to[32][33];
    const int k0 = blockIdx.x * 32;
    const int n0 = blockIdx.y * 32;
    const int tx = threadIdx.x, ty = threadIdx.y;
    const float wl2 = 2.0f * g_WL[(k0 >> 8) * 16 + (n0 >> 8)];
    const int p0 = k0 & 255, q0 = n0 & 255;
#pragma unroll
    for (int i = 0; i < 4; i++) {
        const int r = ty + i * 8;
        tb[r][tx] = base[(size_t)(k0 + r) * NDIM + n0 + tx];
        to[r][tx] = O[(p0 + r) * 256 + q0 + tx];
    }
    __syncthreads();
#pragma unroll
    for (int i = 0; i < 4; i++) {
        const int r = ty + i * 8;   // n-offset within tile
        g_Wt[(size_t)(n0 + r) * KDIM + k0 + tx] = cvt_tf32(tb[tx][r] + wl2 * to[tx][r]);
    }
}

// ---------------------------------------------------------------------------
// Kernel 3: Xc = round_tf32(x), vectorized
// ---------------------------------------------------------------------------
__global__ void lokr_cvt_x(const float4* __restrict__ x) {
    const size_t i = (size_t)blockIdx.x * blockDim.x + threadIdx.x;
    float4 v = x[i];
    v.x = cvt_tf32(v.x); v.y = cvt_tf32(v.y);
    v.z = cvt_tf32(v.z); v.w = cvt_tf32(v.w);
    reinterpret_cast<float4*>(g_Xc)[i] = v;
}

// ---------------------------------------------------------------------------
// Kernel 4: TF32 mma.sync GEMM. BM=64 x BN=128 x BK=32, 3-stage cp.async,
// 3 CTAs/SM. 128 threads = 4 warps; warp grid 2(m) x 2(n); warp tile 32x64.
// ---------------------------------------------------------------------------
struct KIterState {
    const float* pAf;   // running fill pointer (A), advances +BK per iter
    const float* pBf;   // running fill pointer (B)
    uint32_t fsw;       // per-thread swizzled fill offset within a stage
    uint32_t aSw[2];    // pre-swizzled ldsm offsets (A)
    uint32_t bSw[4];    // pre-swizzled ldsm offsets (B)
};

// One k-iteration. sa/fa are compile-time-constant stage bases at call sites.
__device__ __forceinline__ void k_iter(uint32_t sa, uint32_t fa, bool doFill,
                                       KIterState& st, float d[2][8][4]) {
    asm volatile("cp.async.wait_group 1;\n" ::: "memory");
    __syncthreads();
    const uint32_t sb = sa + A_STAGE_BYTES;
    const uint32_t fb = fa + A_STAGE_BYTES;

    uint32_t a[2][4];
    uint32_t b[8][2];

#pragma unroll
    for (int kk = 0; kk < BK / 8; kk++) {
        const uint32_t kb = (uint32_t)(kk * 32);
        // B fragments first: first MMA's operands ready early in the chain.
#pragma unroll
        for (int j = 0; j < 4; j++) {
            uint32_t r0, r1, r2, r3;
            ldsm_x4(r0, r1, r2, r3, sb + (st.bSw[j] ^ kb));
            b[2 * j][0] = r0; b[2 * j + 1][0] = r1;
            b[2 * j][1] = r2; b[2 * j + 1][1] = r3;
        }
#pragma unroll
        for (int i = 0; i < 2; i++)
            ldsm_x4(a[i][0], a[i][1], a[i][2], a[i][3], sa + (st.aSw[i] ^ kb));

        // 1 A-chunk + 2 B-chunks of the next stage's fill (smooth LSU issue)
        if (doFill) {
            cp16(fa + st.fsw + (uint32_t)(kk * 16 * 128),
                 st.pAf + (size_t)kk * 16 * KDIM);
            cp16(fb + st.fsw + (uint32_t)((2 * kk) * 16 * 128),
                 st.pBf + (size_t)(2 * kk) * 16 * KDIM);
            cp16(fb + st.fsw + (uint32_t)((2 * kk + 1) * 16 * 128),
                 st.pBf + (size_t)(2 * kk + 1) * 16 * KDIM);
        }

        // 16 MMAs on this kk's fragments
#pragma unroll
        for (int i = 0; i < 2; i++)
#pragma unroll
            for (int n = 0; n < 8; n++)
                mma_tf32(d[i][n][0], d[i][n][1], d[i][n][2], d[i][n][3],
                         a[i][0], a[i][1], a[i][2], a[i][3], b[n][0], b[n][1]);
    }
    CP_COMMIT();   // one group per k-iter (possibly empty) keeps accounting uniform
    st.pAf += BK;
    st.pBf += BK;
}

__global__ void __launch_bounds__(128, 3)
lokr_gemm_tf32(const float* __restrict__ bias, float* __restrict__ out) {
    extern __shared__ char smem[];
    const uint32_t smem_base = smem_u32(smem);
    const int tid = threadIdx.x;
    const int lane = tid & 31, wid = tid >> 5;
    const int warp_m = (wid & 1) * 32;   // 2 warps along m
    const int warp_n = (wid >> 1) * 64;  // 2 warps along n
    const int n0 = blockIdx.x * BN;
    const int m0 = blockIdx.y * BM;

    const float* Abase = g_Xc + (size_t)m0 * KDIM;
    const float* Bbase = g_Wt + (size_t)n0 * KDIM;

    // Per-thread fill addressing: chunk row = frow + p*16, col4 = tid&7.
    // Stage-local swizzled offset for p=0; p adds 2048 bytes (bits >=11,
    // swizzle-invariant).
    const int frow = tid >> 3, fcol4 = tid & 7;   // frow 0..15
    KIterState st;
    st.fsw = sw128((uint32_t)(frow * 128 + fcol4 * 16));

    // Pre-swizzled ldmatrix offsets; kb in {0,32,64,96} toggles bits 5-6 only,
    // so sw128(off + kb) == sw128(off) ^ kb.
    {
        const uint32_t colp = ((lane >> 4) & 1) * 16;  // k-half select (16B)
#pragma unroll
        for (int i = 0; i < 2; i++)
            st.aSw[i] = sw128((uint32_t)((warp_m + i * 16 + (lane & 15)) * 128) + colp);
#pragma unroll
        for (int j = 0; j < 4; j++)
            st.bSw[j] = sw128((uint32_t)((warp_n + j * 16 + (lane & 15)) * 128) + colp);
    }

    const float* pA0 = Abase + (size_t)frow * KDIM + fcol4 * 4;
    const float* pB0 = Bbase + (size_t)frow * KDIM + fcol4 * 4;

    float d[2][8][4];
#pragma unroll
    for (int i = 0; i < 2; i++)
#pragma unroll
        for (int n = 0; n < 8; n++)
#pragma unroll
            for (int c = 0; c < 4; c++) d[i][n][c] = 0.f;

    // Prologue: fill stages 0 (k=0) and 1 (k=BK)
#pragma unroll
    for (int s = 0; s < STAGES - 1; s++) {
        const uint32_t sa = smem_base + s * STAGE_BYTES;
        const uint32_t sb = sa + A_STAGE_BYTES;
#pragma unroll
        for (int p = 0; p < 4; p++)
            cp16(sa + st.fsw + (uint32_t)(p * 16 * 128),
                 pA0 + (size_t)p * 16 * KDIM + s * BK);
#pragma unroll
        for (int p = 0; p < 8; p++)
            cp16(sb + st.fsw + (uint32_t)(p * 16 * 128),
                 pB0 + (size_t)p * 16 * KDIM + s * BK);
        CP_COMMIT();
    }
    st.pAf = pA0 + (STAGES - 1) * BK;   // first in-loop fill targets k-iter 2
    st.pBf = pB0 + (STAGES - 1) * BK;

    const uint32_t S0 = smem_base;
    const uint32_t S1 = smem_base + STAGE_BYTES;
    const uint32_t S2 = smem_base + 2 * STAGE_BYTES;

    // 126 = 3*42 iterations with compile-time stage bases, then 2 tail iters.
    // Iteration kt consumes stage kt%3 and fills stage (kt+2)%3.
#pragma unroll 1
    for (int t = 0; t < (NKITER - 2) / 3; t++) {
        k_iter(S0, S2, true, st, d);
        k_iter(S1, S0, true, st, d);
        k_iter(S2, S1, true, st, d);
    }
    k_iter(S0, S2, false, st, d);   // kt = 126
    k_iter(S1, S0, false, st, d);   // kt = 127

    // Epilogue: add bias, store float2 per (row, n-block)
#pragma unroll
    for (int i = 0; i < 2; i++) {
        const int row = m0 + warp_m + i * 16 + (lane >> 2);
#pragma unroll
        for (int n = 0; n < 8; n++) {
            const int col = n0 + warp_n + n * 8 + (lane & 3) * 2;
            const float bv0 = bias[col], bv1 = bias[col + 1];
            float2 v0 = make_float2(d[i][n][0] + bv0, d[i][n][1] + bv1);
            float2 v1 = make_float2(d[i][n][2] + bv0, d[i][n][3] + bv1);
            *reinterpret_cast<float2*>(out + (size_t)row * NDIM + col) = v0;
            *reinterpret_cast<float2*>(out + (size_t)(row + 8) * NDIM + col) = v1;
        }
    }
}

// ---------------------------------------------------------------------------
// Launch
// ---------------------------------------------------------------------------
extern "C" void kernel_launch(void* const* d_in, const int* in_sizes, int n_in,
                              void* d_out, int out_size) {
    (void)in_sizes; (void)n_in; (void)out_size;
    const float* x    = (const float*)d_in[0];
    const float* base = (const float*)d_in[1];
    const float* bias = (const float*)d_in[2];
    const float* la   = (const float*)d_in[3];
    const float* lb   = (const float*)d_in[4];
    const float* O    = (const float*)d_in[5];
    float* out = (float*)d_out;

    lokr_compute_wl<<<1, 256>>>(la, lb);

    dim3 gw(KDIM / 32, NDIM / 32);
    lokr_build_wt<<<gw, dim3(32, 8)>>>(base, O);

    const size_t n4 = (size_t)MDIM * KDIM / 4;   // 16M float4
    lokr_cvt_x<<<(unsigned)(n4 / 256), 256>>>((const float4*)x);

    cudaFuncSetAttribute(lokr_gemm_tf32, cudaFuncAttributeMaxDynamicSharedMemorySize, SMEM_TOTAL);
    dim3 gg(NDIM / BN, MDIM / BM);
    lokr_gemm_tf32<<<gg, 128, SMEM_TOTAL>>>(bias, out);
}

// round 17
// speedup vs baseline: 1.3150x; 1.0337x over previous
#include <cuda_runtime.h>
#include <cstdint>

// ---------------------------------------------------------------------------
// LokrLinear: out = x @ (base_kernel + 2.0 * kron(lora_A@lora_B, O)) + bias
//
// Base-ISA path (tcgen05 is 'a'-gated; harness builds compute_103 PTX):
//   1) WL = lora_A @ lora_B (16x16)
//   2) Wt[n][k] = round_tf32(COMP * (base[k][n] + 2*WL[..]*O[..]))
//   3) out = x @ Wt^T + bias via mma.sync.m16n8k8.tf32, cp.async 3-stage
//      pipeline, SW128-swizzled smem, ldmatrix fragment loads.
//
// R14 (resubmitted after infra failure): drop the separate tf32-rounding pass
// over x (512MB of DRAM traffic, ~100us). HMMA-tf32 TRUNCATES fp32 operands;
// truncation of x introduces a multiplicative bias E[delta] ~= 0.72*2^-11 on
// every dot product, which we cancel by scaling Wt by COMP = 1 + 3.52e-4
// before its RNA rounding. The remaining truncation noise is zero-mean
// (~2.8e-4/term), keeping rel_err well under 1e-3. GEMM kernel itself is the
// proven R13 config: 128-thread CTAs, BM=64 x BN=128, warp tile 32x64,
// 3 CTAs/SM, 3-stage cp.async, k-loop unrolled by 3 w/ compile-time stages.
// ---------------------------------------------------------------------------

static constexpr int MDIM = 16384;
static constexpr int KDIM = 4096;
static constexpr int NDIM = 4096;

static constexpr int BM = 64;
static constexpr int BN = 128;
static constexpr int BK = 32;                 // 32 tf32 = 128B row (SW128 atom)
static constexpr int STAGES = 3;
static constexpr int NKITER = KDIM / BK;      // 128
static constexpr int A_STAGE_BYTES = BM * BK * 4;   // 8192
static constexpr int B_STAGE_BYTES = BN * BK * 4;   // 16384
static constexpr int STAGE_BYTES = A_STAGE_BYTES + B_STAGE_BYTES; // 24576
static constexpr int SMEM_TOTAL = STAGES * STAGE_BYTES;           // 73728

// Bias compensation for HW truncation of the (unrounded) x operand:
// E[rel truncation loss] = 2^-11 * E[1/mantissa] ~= 2^-11 * 0.7213 = 3.521e-4
static constexpr float COMP = 1.0003521f;

// Device scratch (static __device__ arrays are the allowed scratch mechanism)
__device__ float g_WL[256];                           // (A@B) 16x16
__device__ float g_Wt[(size_t)NDIM * (size_t)KDIM];   // W_eff^T: [N][K], K contiguous

// ---------------------------------------------------------------------------
// Helpers
// ---------------------------------------------------------------------------
__device__ __forceinline__ uint32_t smem_u32(const void* p) {
    uint32_t a;
    asm("{ .reg .u64 t; cvta.to.shared.u64 t, %1; cvt.u32.u64 %0, t; }" : "=r"(a) : "l"(p));
    return a;
}

__device__ __forceinline__ float cvt_tf32(float x) {
    uint32_t o;
    asm("cvt.rna.tf32.f32 %0, %1;" : "=r"(o) : "f"(x));
    return __uint_as_float(o);
}

__device__ __forceinline__ void cp16(uint32_t saddr, const float* g) {
    asm volatile("cp.async.cg.shared.global [%0], [%1], 16;\n" :: "r"(saddr), "l"(g));
}
#define CP_COMMIT() asm volatile("cp.async.commit_group;\n" ::: "memory")

__device__ __forceinline__ void ldsm_x4(uint32_t& r0, uint32_t& r1, uint32_t& r2, uint32_t& r3,
                                        uint32_t addr) {
    asm volatile("ldmatrix.sync.aligned.m8n8.x4.shared.b16 {%0,%1,%2,%3}, [%4];\n"
                 : "=r"(r0), "=r"(r1), "=r"(r2), "=r"(r3) : "r"(addr));
}

__device__ __forceinline__ void mma_tf32(float& d0, float& d1, float& d2, float& d3,
                                         uint32_t a0, uint32_t a1, uint32_t a2, uint32_t a3,
                                         uint32_t b0, uint32_t b1) {
    asm volatile(
        "mma.sync.aligned.m16n8k8.row.col.f32.tf32.tf32.f32 "
        "{%0,%1,%2,%3}, {%4,%5,%6,%7}, {%8,%9}, {%0,%1,%2,%3};\n"
        : "+f"(d0), "+f"(d1), "+f"(d2), "+f"(d3)
        : "r"(a0), "r"(a1), "r"(a2), "r"(a3), "r"(b0), "r"(b1));
}

__device__ __forceinline__ uint32_t sw128(uint32_t off) {
    return off ^ ((off >> 3) & 0x70);
}

// ---------------------------------------------------------------------------
// Kernel 1: WL = lora_A @ lora_B (16x16)
// ---------------------------------------------------------------------------
__global__ void lokr_compute_wl(const float* __restrict__ A, const float* __restrict__ B) {
    const int i = threadIdx.x >> 4, j = threadIdx.x & 15;
    float s = 0.f;
#pragma unroll
    for (int r = 0; r < 16; r++) s += A[i * 16 + r] * B[r * 16 + j];
    g_WL[threadIdx.x] = s;
}

// ---------------------------------------------------------------------------
// Kernel 2: Wt[n][k] = round_tf32(COMP*(base[k][n] + 2*WL[..]*O[..]))
// (transpose through padded SMEM tiles; all global accesses coalesced)
// ---------------------------------------------------------------------------
__global__ void lokr_build_wt(const float* __restrict__ base, const float* __restrict__ O) {
    __shared__ float tb[32][33];
    __shared__ float to[32][33];
    const int k0 = blockIdx.x * 32;
    const int n0 = blockIdx.y * 32;
    const int tx = threadIdx.x, ty = threadIdx.y;
    const float wl2 = 2.0f * g_WL[(k0 >> 8) * 16 + (n0 >> 8)];
    const int p0 = k0 & 255, q0 = n0 & 255;
#pragma unroll
    for (int i = 0; i < 4; i++) {
        const int r = ty + i * 8;
        tb[r][tx] = base[(size_t)(k0 + r) * NDIM + n0 + tx];
        to[r][tx] = O[(p0 + r) * 256 + q0 + tx];
    }
    __syncthreads();
#pragma unroll
    for (int i = 0; i < 4; i++) {
        const int r = ty + i * 8;   // n-offset within tile
        g_Wt[(size_t)(n0 + r) * KDIM + k0 + tx] =
            cvt_tf32(COMP * (tb[tx][r] + wl2 * to[tx][r]));
    }
}

// ---------------------------------------------------------------------------
// Kernel 3: TF32 mma.sync GEMM. BM=64 x BN=128 x BK=32, 3-stage cp.async,
// 3 CTAs/SM. 128 threads = 4 warps; warp grid 2(m) x 2(n); warp tile 32x64.
// A operand = raw fp32 x (HW truncates to tf32; bias compensated in Wt).
// ---------------------------------------------------------------------------
struct KIterState {
    const float* pAf;   // running fill pointer (A), advances +BK per iter
    const float* pBf;   // running fill pointer (B)
    uint32_t fsw;       // per-thread swizzled fill offset within a stage
    uint32_t aSw[2];    // pre-swizzled ldsm offsets (A)
    uint32_t bSw[4];    // pre-swizzled ldsm offsets (B)
};

// One k-iteration. sa/fa are compile-time-constant stage bases at call sites.
__device__ __forceinline__ void k_iter(uint32_t sa, uint32_t fa, bool doFill,
                                       KIterState& st, float d[2][8][4]) {
    asm volatile("cp.async.wait_group 1;\n" ::: "memory");
    __syncthreads();
    const uint32_t sb = sa + A_STAGE_BYTES;
    const uint32_t fb = fa + A_STAGE_BYTES;

    uint32_t a[2][4];
    uint32_t b[8][2];

#pragma unroll
    for (int kk = 0; kk < BK / 8; kk++) {
        const uint32_t kb = (uint32_t)(kk * 32);
        // B fragments first: first MMA's operands ready early in the chain.
#pragma unroll
        for (int j = 0; j < 4; j++) {
            uint32_t r0, r1, r2, r3;
            ldsm_x4(r0, r1, r2, r3, sb + (st.bSw[j] ^ kb));
            b[2 * j][0] = r0; b[2 * j + 1][0] = r1;
            b[2 * j][1] = r2; b[2 * j + 1][1] = r3;
        }
#pragma unroll
        for (int i = 0; i < 2; i++)
            ldsm_x4(a[i][0], a[i][1], a[i][2], a[i][3], sa + (st.aSw[i] ^ kb));

        // 1 A-chunk + 2 B-chunks of the next stage's fill (smooth LSU issue)
        if (doFill) {
            cp16(fa + st.fsw + (uint32_t)(kk * 16 * 128),
                 st.pAf + (size_t)kk * 16 * KDIM);
            cp16(fb + st.fsw + (uint32_t)((2 * kk) * 16 * 128),
                 st.pBf + (size_t)(2 * kk) * 16 * KDIM);
            cp16(fb + st.fsw + (uint32_t)((2 * kk + 1) * 16 * 128),
                 st.pBf + (size_t)(2 * kk + 1) * 16 * KDIM);
        }

        // 16 MMAs on this kk's fragments
#pragma unroll
        for (int i = 0; i < 2; i++)
#pragma unroll
            for (int n = 0; n < 8; n++)
                mma_tf32(d[i][n][0], d[i][n][1], d[i][n][2], d[i][n][3],
                         a[i][0], a[i][1], a[i][2], a[i][3], b[n][0], b[n][1]);
    }
    CP_COMMIT();   // one group per k-iter (possibly empty) keeps accounting uniform
    st.pAf += BK;
    st.pBf += BK;
}

__global__ void __launch_bounds__(128, 3)
lokr_gemm_tf32(const float* __restrict__ X, const float* __restrict__ bias,
               float* __restrict__ out) {
    extern __shared__ char smem[];
    const uint32_t smem_base = smem_u32(smem);
    const int tid = threadIdx.x;
    const int lane = tid & 31, wid = tid >> 5;
    const int warp_m = (wid & 1) * 32;   // 2 warps along m
    const int warp_n = (wid >> 1) * 64;  // 2 warps along n
    const int n0 = blockIdx.x * BN;
    const int m0 = blockIdx.y * BM;

    const float* Abase = X + (size_t)m0 * KDIM;
    const float* Bbase = g_Wt + (size_t)n0 * KDIM;

    // Per-thread fill addressing: chunk row = frow + p*16, col4 = tid&7.
    const int frow = tid >> 3, fcol4 = tid & 7;   // frow 0..15
    KIterState st;
    st.fsw = sw128((uint32_t)(frow * 128 + fcol4 * 16));

    // Pre-swizzled ldmatrix offsets; kb in {0,32,64,96} toggles bits 5-6 only,
    // so sw128(off + kb) == sw128(off) ^ kb.
    {
        const uint32_t colp = ((lane >> 4) & 1) * 16;  // k-half select (16B)
#pragma unroll
        for (int i = 0; i < 2; i++)
            st.aSw[i] = sw128((uint32_t)((warp_m + i * 16 + (lane & 15)) * 128) + colp);
#pragma unroll
        for (int j = 0; j < 4; j++)
            st.bSw[j] = sw128((uint32_t)((warp_n + j * 16 + (lane & 15)) * 128) + colp);
    }

    const float* pA0 = Abase + (size_t)frow * KDIM + fcol4 * 4;
    const float* pB0 = Bbase + (size_t)frow * KDIM + fcol4 * 4;

    float d[2][8][4];
#pragma unroll
    for (int i = 0; i < 2; i++)
#pragma unroll
        for (int n = 0; n < 8; n++)
#pragma unroll
            for (int c = 0; c < 4; c++) d[i][n][c] = 0.f;

    // Prologue: fill stages 0 (k=0) and 1 (k=BK)
#pragma unroll
    for (int s = 0; s < STAGES - 1; s++) {
        const uint32_t sa = smem_base + s * STAGE_BYTES;
        const uint32_t sb = sa + A_STAGE_BYTES;
#pragma unroll
        for (int p = 0; p < 4; p++)
            cp16(sa + st.fsw + (uint32_t)(p * 16 * 128),
                 pA0 + (size_t)p * 16 * KDIM + s * BK);
#pragma unroll
        for (int p = 0; p < 8; p++)
            cp16(sb + st.fsw + (uint32_t)(p * 16 * 128),
                 pB0 + (size_t)p * 16 * KDIM + s * BK);
        CP_COMMIT();
    }
    st.pAf = pA0 + (STAGES - 1) * BK;   // first in-loop fill targets k-iter 2
    st.pBf = pB0 + (STAGES - 1) * BK;

    const uint32_t S0 = smem_base;
    const uint32_t S1 = smem_base + STAGE_BYTES;
    const uint32_t S2 = smem_base + 2 * STAGE_BYTES;

    // 126 = 3*42 iterations with compile-time stage bases, then 2 tail iters.
    // Iteration kt consumes stage kt%3 and fills stage (kt+2)%3.
#pragma unroll 1
    for (int t = 0; t < (NKITER - 2) / 3; t++) {
        k_iter(S0, S2, true, st, d);
        k_iter(S1, S0, true, st, d);
        k_iter(S2, S1, true, st, d);
    }
    k_iter(S0, S2, false, st, d);   // kt = 126
    k_iter(S1, S0, false, st, d);   // kt = 127

    // Epilogue: add bias, store float2 per (row, n-block)
#pragma unroll
    for (int i = 0; i < 2; i++) {
        const int row = m0 + warp_m + i * 16 + (lane >> 2);
#pragma unroll
        for (int n = 0; n < 8; n++) {
            const int col = n0 + warp_n + n * 8 + (lane & 3) * 2;
            const float bv0 = bias[col], bv1 = bias[col + 1];
            float2 v0 = make_float2(d[i][n][0] + bv0, d[i][n][1] + bv1);
            float2 v1 = make_float2(d[i][n][2] + bv0, d[i][n][3] + bv1);
            *reinterpret_cast<float2*>(out + (size_t)row * NDIM + col) = v0;
            *reinterpret_cast<float2*>(out + (size_t)(row + 8) * NDIM + col) = v1;
        }
    }
}

// ---------------------------------------------------------------------------
// Launch
// ---------------------------------------------------------------------------
extern "C" void kernel_launch(void* const* d_in, const int* in_sizes, int n_in,
                              void* d_out, int out_size) {
    (void)in_sizes; (void)n_in; (void)out_size;
    const float* x    = (const float*)d_in[0];
    const float* base = (const float*)d_in[1];
    const float* bias = (const float*)d_in[2];
    const float* la   = (const float*)d_in[3];
    const float* lb   = (const float*)d_in[4];
    const float* O    = (const float*)d_in[5];
    float* out = (float*)d_out;

    lokr_compute_wl<<<1, 256>>>(la, lb);

    dim3 gw(KDIM / 32, NDIM / 32);
    lokr_build_wt<<<gw, dim3(32, 8)>>>(base, O);

    cudaFuncSetAttribute(lokr_gemm_tf32, cudaFuncAttributeMaxDynamicSharedMemorySize, SMEM_TOTAL);
    dim3 gg(NDIM / BN, MDIM / BM);
    lokr_gemm_tf32<<<gg, 128, SMEM_TOTAL>>>(x, bias, out);
}